// round 3
// baseline (speedup 1.0000x reference)
#include <cuda_runtime.h>
#include <cuda_bf16.h>
#include <cstdint>

// Inputs (metadata order):
//   d_in[0] = x      float32 [262144]   (1 MB, random-gathered -> keep in L1)
//   d_in[1] = A_vals float32 [NNZ]      (streamed once -> L2-only, bypass L1)
//   d_in[2] = A_rows int32   [NNZ]      (streamed once -> L2-only, bypass L1)
//   d_in[3] = A_cols int32   [NNZ]      (streamed once -> L2-only, bypass L1)
// Output: float32 [262144]

// Streaming 16B load that does NOT allocate in L1 (caches at L2 only).
__device__ __forceinline__ float4 ldcg_f4(const float4* p) {
    float4 v;
    asm volatile("ld.global.cg.v4.f32 {%0,%1,%2,%3}, [%4];"
                 : "=f"(v.x), "=f"(v.y), "=f"(v.z), "=f"(v.w) : "l"(p));
    return v;
}
__device__ __forceinline__ int4 ldcg_i4(const int4* p) {
    int4 v;
    asm volatile("ld.global.cg.v4.b32 {%0,%1,%2,%3}, [%4];"
                 : "=r"(v.x), "=r"(v.y), "=r"(v.z), "=r"(v.w) : "l"(p));
    return v;
}

// x gather: allocate in L1 with evict_last so the 1MB x working set owns L1.
__device__ __forceinline__ float ldg_x(const float* p) {
    float v;
    asm volatile("ld.global.nc.L1::evict_last.f32 %0, [%1];" : "=f"(v) : "l"(p));
    return v;
}

// 8 nnz per thread: two float4/int4 stream loads per array, 8 gathers, 8 REDs.
__global__ void __launch_bounds__(256) coo_spmv_kernel(
    const float*  __restrict__ x,
    const float4* __restrict__ vals4,
    const int4*   __restrict__ rows4,
    const int4*   __restrict__ cols4,
    float*        __restrict__ out,
    int nnz4)   // number of 4-element groups
{
    int i = (blockIdx.x * blockDim.x + threadIdx.x) * 2;  // two groups per thread
    if (i >= nnz4) return;

    // Front-batch all streaming loads for max MLP.
    float4 v0 = ldcg_f4(&vals4[i]);
    int4   r0 = ldcg_i4(&rows4[i]);
    int4   c0 = ldcg_i4(&cols4[i]);

    bool second = (i + 1) < nnz4;
    float4 v1; int4 r1, c1;
    if (second) {
        v1 = ldcg_f4(&vals4[i + 1]);
        r1 = ldcg_i4(&rows4[i + 1]);
        c1 = ldcg_i4(&cols4[i + 1]);
    }

    // Gathers (L1-resident x, evict_last).
    float x00 = ldg_x(&x[c0.x]);
    float x01 = ldg_x(&x[c0.y]);
    float x02 = ldg_x(&x[c0.z]);
    float x03 = ldg_x(&x[c0.w]);

    atomicAdd(&out[r0.x], v0.x * x00);
    atomicAdd(&out[r0.y], v0.y * x01);
    atomicAdd(&out[r0.z], v0.z * x02);
    atomicAdd(&out[r0.w], v0.w * x03);

    if (second) {
        float x10 = ldg_x(&x[c1.x]);
        float x11 = ldg_x(&x[c1.y]);
        float x12 = ldg_x(&x[c1.z]);
        float x13 = ldg_x(&x[c1.w]);

        atomicAdd(&out[r1.x], v1.x * x10);
        atomicAdd(&out[r1.y], v1.y * x11);
        atomicAdd(&out[r1.z], v1.z * x12);
        atomicAdd(&out[r1.w], v1.w * x13);
    }
}

// Tail handler for nnz not divisible by 4 (unused for this shape, kept safe).
__global__ void coo_spmv_tail_kernel(
    const float* __restrict__ x,
    const float* __restrict__ vals,
    const int*   __restrict__ rows,
    const int*   __restrict__ cols,
    float*       __restrict__ out,
    int start, int nnz)
{
    int i = start + blockIdx.x * blockDim.x + threadIdx.x;
    if (i < nnz) {
        atomicAdd(&out[rows[i]], vals[i] * __ldg(&x[cols[i]]));
    }
}

extern "C" void kernel_launch(void* const* d_in, const int* in_sizes, int n_in,
                              void* d_out, int out_size) {
    const float* x    = (const float*)d_in[0];
    const float* vals = (const float*)d_in[1];
    const int*   rows = (const int*)d_in[2];
    const int*   cols = (const int*)d_in[3];
    float* out = (float*)d_out;

    const int nnz = in_sizes[1];

    // Zero-init output (harness poisons it).
    cudaMemsetAsync(out, 0, (size_t)out_size * sizeof(float), 0);

    // Main vectorized COO pass: 8 nnz per thread.
    int nnz4 = nnz / 4;
    if (nnz4 > 0) {
        int threads = 256;
        int groups_per_block = threads * 2;            // each thread: 2 groups of 4
        int blocks = (nnz4 + groups_per_block - 1) / groups_per_block;
        coo_spmv_kernel<<<blocks, threads>>>(
            x, (const float4*)vals, (const int4*)rows, (const int4*)cols, out, nnz4);
    }

    // Tail (nnz % 4), skipped when empty.
    int tail_start = nnz4 * 4;
    int tail = nnz - tail_start;
    if (tail > 0) {
        coo_spmv_tail_kernel<<<(tail + 255) / 256, 256>>>(
            x, vals, rows, cols, out, tail_start, nnz);
    }
}